// round 14
// baseline (speedup 1.0000x reference)
#include <cuda_runtime.h>
#include <float.h>

// ROI max pool, TWO kernels, no scratch output:
//  A) prepare: register transpose [2,256,50,50] -> g_feat_t [2,50,50,256]
//     + per-(roi,bin) bounds into g_meta.
//  B) pool: warp = 4 consecutive bins x 32 channels. lane = (cq, dj):
//     cq = lane>>2 channel-quad (float4), dj = lane&3 bin offset.
//     Loads: LDG.128, lanes of equal dj are channel-contiguous.
//     Stores: per-channel 4-bin 16B runs -> 8 sectors/STG (4x fewer than
//     scattered). No smem, no syncthreads, no reshape kernel.

#define OUTP 7
#define NBINS 49
#define CCH  256
#define HH   50
#define WW   50
#define HWSZ (HH * WW)
#define BB   2

#define TBLKS (79 * 8 * 2)     // transpose blocks
#define PBLKS 25               // prep blocks

__device__ __align__(16) float g_feat_t[BB * HWSZ * CCH];   // 5.12 MB
__device__ int4 g_meta[128 * NBINS];

// ---------------- A) prepare: transpose + prep fused ----------------
__global__ __launch_bounds__(256) void prepare_kernel(
    const float* __restrict__ feat, const float* __restrict__ rois)
{
    int bi = blockIdx.x;
    if (bi < TBLKS) {
        int b   = bi / (79 * 8);
        int rem = bi - b * (79 * 8);
        int cy  = rem / 79;
        int hx  = rem - cy * 79;
        int c0   = cy * 32 + (threadIdx.x >> 5) * 4;
        int lane = threadIdx.x & 31;
        int hw   = hx * 32 + lane;
        if (hw < HWSZ) {
            const float* src = feat + ((size_t)b * CCH + c0) * HWSZ + hw;
            float4 o;
            o.x = __ldg(src);
            o.y = __ldg(src + HWSZ);
            o.z = __ldg(src + 2 * HWSZ);
            o.w = __ldg(src + 3 * HWSZ);
            *(float4*)(g_feat_t + ((size_t)b * HWSZ + hw) * CCH + c0) = o;
        }
    } else {
        int t = (bi - TBLKS) * 256 + threadIdx.x;
        if (t >= 128 * NBINS) return;
        int n  = t / NBINS;
        int ij = t - n * NBINS;
        int i  = ij / OUTP;
        int j  = ij - i * OUTP;

        const float* r = rois + n * 5;
        int im = (int)rintf(r[0]);
        int x1 = (int)rintf(r[1] * 0.0625f);
        int y1 = (int)rintf(r[2] * 0.0625f);
        int x2 = (int)rintf(r[3] * 0.0625f);
        int y2 = (int)rintf(r[4] * 0.0625f);
        unsigned h = (unsigned)(y2 - y1 + 1);
        unsigned w = (unsigned)(x2 - x1 + 1);

        int ys = (int)((unsigned)(i * h) / 7u) + y1;
        int ye = (int)(((unsigned)((i + 1) * h) + 6u) / 7u) + y1;
        int xs = (int)((unsigned)(j * w) / 7u) + x1;
        int xe = (int)(((unsigned)((j + 1) * w) + 6u) / 7u) + x1;
        ye = min(ye, HH);  xe = min(xe, WW);

        int4 m;
        m.x = im * HWSZ + ys * WW + xs;   // flat spatial start
        m.y = ye - ys;                    // rows, 1..8
        m.z = xe - xs - 1;                // wm1, 0..7
        m.w = 0;
        g_meta[t] = m;
    }
}

__device__ __forceinline__ float4 fmax4(float4 a, float4 b)
{
    return make_float4(fmaxf(a.x, b.x), fmaxf(a.y, b.y),
                       fmaxf(a.z, b.z), fmaxf(a.w, b.w));
}

// ---------------- B) pool ----------------
// warp-task t: n = t/104, rem = t%104, cg8 = rem/13, q = rem%13.
// lane: dj = lane&3 (bin 4q+dj), cq = lane>>2 (channels cg8*32 + cq*4 ..+3).
// grid 1664 CTAs x 256 thr (8 warp-tasks per CTA). 13312 tasks total.
__global__ __launch_bounds__(256) void roi_pool_kernel(float* __restrict__ out)
{
    int t = blockIdx.x * 8 + (threadIdx.x >> 5);      // warp task
    int lane = threadIdx.x & 31;
    int dj   = lane & 3;
    int cq   = lane >> 2;

    int n    = t / 104;
    int rem  = t - n * 104;
    int cg8  = rem / 13;
    int q    = rem - cg8 * 13;

    int ijraw = 4 * q + dj;
    int ij    = min(ijraw, NBINS - 1);

    int4 m = __ldg(&g_meta[n * NBINS + ij]);
    int rows = m.y;
    int wm1  = m.z;

    // float4 index: position*64 + cg8*8 + cq
    const float4* base = (const float4*)g_feat_t
                       + (size_t)m.x * (CCH / 4) + cg8 * 8 + cq;

    int rmax = __reduce_max_sync(0xffffffffu, (unsigned)rows);

    float4 acc = make_float4(-FLT_MAX, -FLT_MAX, -FLT_MAX, -FLT_MAX);
    for (int r = 0; r < rmax; ++r) {
        int rr = min(r, rows - 1);                     // per-lane clamp
        const float4* row = base + (size_t)rr * (WW * (CCH / 4));
        // chunk 1: slots 0..3 (clamped; dups benign for max)
        float4 v0 = __ldg(row);
        float4 v1 = __ldg(row + min(1, wm1) * (CCH / 4));
        float4 v2 = __ldg(row + min(2, wm1) * (CCH / 4));
        float4 v3 = __ldg(row + min(3, wm1) * (CCH / 4));
        acc = fmax4(acc, fmax4(fmax4(v0, v1), fmax4(v2, v3)));
        // chunk 2: slots 4..7 (per-lane predicated)
        if (wm1 >= 4) {
            float4 v4 = __ldg(row + 4 * (CCH / 4));
            float4 v5 = __ldg(row + min(5, wm1) * (CCH / 4));
            float4 v6 = __ldg(row + min(6, wm1) * (CCH / 4));
            float4 v7 = __ldg(row + min(7, wm1) * (CCH / 4));
            acc = fmax4(acc, fmax4(fmax4(v4, v5), fmax4(v6, v7)));
        }
    }

    // store: out[n][c][ijraw], c = cg8*32 + cq*4 + e.
    // lanes with equal cq and dj=0..3 form 16B-contiguous runs.
    if (ijraw < NBINS) {
        int c0 = cg8 * 32 + cq * 4;
        float* dst = out + ((size_t)n * CCH + c0) * NBINS + ijraw;
        dst[0 * NBINS] = acc.x;
        dst[1 * NBINS] = acc.y;
        dst[2 * NBINS] = acc.z;
        dst[3 * NBINS] = acc.w;
    }
}

extern "C" void kernel_launch(void* const* d_in, const int* in_sizes, int n_in,
                              void* d_out, int out_size)
{
    const float* feat = (const float*)d_in[0];
    const float* rois = (const float*)d_in[1];
    float* out = (float*)d_out;

    prepare_kernel<<<TBLKS + PBLKS, 256>>>(feat, rois);

    // 13312 warp tasks / 8 per CTA = 1664 CTAs
    roi_pool_kernel<<<1664, 256>>>(out);
}

// round 15
// speedup vs baseline: 1.2881x; 1.2881x over previous
#include <cuda_runtime.h>
#include <float.h>

// ROI max pool (R9 architecture, register-dieted pool):
//  A) prepare: register transpose [2,256,50,50] -> g_feat_t [2,50,50,256]
//     + per-(roi,bin) bounds into g_meta (one fused launch)
//  B) pool: 6272 blocks x 64 thr; warp = ONE bin x 128 consecutive channels
//     (lanes = channels: proven coalesced-load pattern). Chunked 4-load
//     inner loop + 32-bit indexing -> low regs -> high occupancy.
//     float4 store to bin-major g_tmp.
//  C) reshape: g_tmp[n][ij][c] -> out[n][c][ij] (smem tiles, float4 reads).

#define OUTP 7
#define NBINS 49
#define CCH  256
#define HH   50
#define WW   50
#define HWSZ (HH * WW)
#define BB   2
#define CS4  (CCH / 4)          // 64 float4 per spatial position
#define RS4  (WW * CS4)         // 3200 float4 per feature row

#define TBLKS (79 * 8 * 2)
#define PBLKS 25

__device__ __align__(16) float g_feat_t[BB * HWSZ * CCH];   // 5.12 MB
__device__ __align__(16) float g_tmp[128 * NBINS * CCH];    // 6.42 MB
__device__ int4 g_meta[128 * NBINS];

// ---------------- A) prepare: transpose + prep fused ----------------
__global__ __launch_bounds__(256) void prepare_kernel(
    const float* __restrict__ feat, const float* __restrict__ rois)
{
    int bi = blockIdx.x;
    if (bi < TBLKS) {
        int b   = bi / (79 * 8);
        int rem = bi - b * (79 * 8);
        int cy  = rem / 79;
        int hx  = rem - cy * 79;
        int c0   = cy * 32 + (threadIdx.x >> 5) * 4;
        int lane = threadIdx.x & 31;
        int hw   = hx * 32 + lane;
        if (hw < HWSZ) {
            const float* src = feat + (b * CCH + c0) * HWSZ + hw;
            float4 o;
            o.x = __ldg(src);
            o.y = __ldg(src + HWSZ);
            o.z = __ldg(src + 2 * HWSZ);
            o.w = __ldg(src + 3 * HWSZ);
            *(float4*)(g_feat_t + ((b * HWSZ + hw) * CCH + c0)) = o;
        }
    } else {
        int t = (bi - TBLKS) * 256 + threadIdx.x;
        if (t >= 128 * NBINS) return;
        int n  = t / NBINS;
        int ij = t - n * NBINS;
        int i  = ij / OUTP;
        int j  = ij - i * OUTP;

        const float* r = rois + n * 5;
        int im = (int)rintf(r[0]);
        int x1 = (int)rintf(r[1] * 0.0625f);
        int y1 = (int)rintf(r[2] * 0.0625f);
        int x2 = (int)rintf(r[3] * 0.0625f);
        int y2 = (int)rintf(r[4] * 0.0625f);
        unsigned h = (unsigned)(y2 - y1 + 1);
        unsigned w = (unsigned)(x2 - x1 + 1);

        int ys = (int)((unsigned)(i * h) / 7u) + y1;
        int ye = (int)(((unsigned)((i + 1) * h) + 6u) / 7u) + y1;
        int xs = (int)((unsigned)(j * w) / 7u) + x1;
        int xe = (int)(((unsigned)((j + 1) * w) + 6u) / 7u) + x1;
        ye = min(ye, HH);  xe = min(xe, WW);

        int4 m;
        m.x = im * HWSZ + ys * WW + xs;
        m.y = ye - ys;
        m.z = xe - xs - 1;
        m.w = 0;
        g_meta[t] = m;
    }
}

__device__ __forceinline__ float4 fmax4(float4 a, float4 b)
{
    return make_float4(fmaxf(a.x, b.x), fmaxf(a.y, b.y),
                       fmaxf(a.z, b.z), fmaxf(a.w, b.w));
}

// ---------------- B) pool: 6272 x 64, low-reg ----------------
__global__ __launch_bounds__(64, 28) void roi_pool_kernel(void)
{
    int task = blockIdx.x;                 // n*NBINS + ij
    int tc   = threadIdx.x;                // cg*32 + lane packed: 0..63

    int4 m = __ldg(&g_meta[task]);
    int wm1 = m.z;

    // 32-bit float4 indexing throughout (max index < 2^20)
    const float4* base = (const float4*)g_feat_t + (unsigned)(m.x * CS4 + tc);

    // hoisted clamped offsets (warp-uniform)
    int o1 = min(1, wm1) * CS4;
    int o2 = min(2, wm1) * CS4;
    int o3 = min(3, wm1) * CS4;
    int o5 = min(5, wm1) * CS4;
    int o6 = min(6, wm1) * CS4;
    int o7 = min(7, wm1) * CS4;

    float4 acc = make_float4(-FLT_MAX, -FLT_MAX, -FLT_MAX, -FLT_MAX);
    int rows = m.y;
    for (int r = 0; r < rows; ++r) {
        const float4* row = base + r * RS4;
        float4 v0 = __ldg(row);
        float4 v1 = __ldg(row + o1);
        float4 v2 = __ldg(row + o2);
        float4 v3 = __ldg(row + o3);
        acc = fmax4(acc, fmax4(fmax4(v0, v1), fmax4(v2, v3)));
        if (wm1 >= 4) {                    // warp-uniform branch
            v0 = __ldg(row + 4 * CS4);     // reuse temporaries
            v1 = __ldg(row + o5);
            v2 = __ldg(row + o6);
            v3 = __ldg(row + o7);
            acc = fmax4(acc, fmax4(fmax4(v0, v1), fmax4(v2, v3)));
        }
    }

    ((float4*)g_tmp)[(unsigned)(task * (CCH / 4) + tc)] = acc;
}

// ---------------- C) reshape: g_tmp[n][ij][c] -> out[n][c][ij] -------------
__global__ __launch_bounds__(256) void reshape_kernel(float* __restrict__ out)
{
    __shared__ float s[NBINS][33];
    int c0 = blockIdx.x * 32;
    int n  = blockIdx.y;
    int t  = threadIdx.x;

    const float4* src4 = (const float4*)(g_tmp + (n * NBINS * CCH + c0));
    for (int p = t; p < NBINS * 8; p += 256) {
        int ij = p >> 3;
        int q  = p & 7;
        float4 v = __ldg(src4 + ij * (CCH / 4) + q);
        s[ij][q * 4 + 0] = v.x;
        s[ij][q * 4 + 1] = v.y;
        s[ij][q * 4 + 2] = v.z;
        s[ij][q * 4 + 3] = v.w;
    }
    __syncthreads();

    float* dst = out + (n * CCH + c0) * NBINS;
    for (int p = t; p < 32 * NBINS; p += 256) {
        int c  = p / NBINS;
        int ij = p - c * NBINS;
        dst[p] = s[ij][c];
    }
}

extern "C" void kernel_launch(void* const* d_in, const int* in_sizes, int n_in,
                              void* d_out, int out_size)
{
    const float* feat = (const float*)d_in[0];
    const float* rois = (const float*)d_in[1];
    float* out = (float*)d_out;

    prepare_kernel<<<TBLKS + PBLKS, 256>>>(feat, rois);

    roi_pool_kernel<<<128 * NBINS, 64>>>();

    reshape_kernel<<<dim3(8, 128), 256>>>(out);
}